// round 5
// baseline (speedup 1.0000x reference)
#include <cuda_runtime.h>
typedef unsigned long long u64;

// B=32, CIN=COUT=32, H=W=128, M1=M2=16, NMODE=32.
__device__ float4 g_Xw[1024 * 128 * 8];  // [bc][h][kq] (re_ky0,re_ky1,im_ky0,im_ky1) 16MB
__device__ float2 g_Xf[512 * 1024];      // [f][bc]  4MB
__device__ float2 g_Yf[512 * 1024];      // [f][bo]  4MB

// Pre-splatted twiddle tables (built once by k0).
__device__ u64 gT1[2048 * 2];   // [w][ky]{C,S}        fwd W-DFT
__device__ u64 gE2[4096 * 2];   // [h][kxi]{er,ei}     fwd H-DFT  (e^{-i})
__device__ u64 gE3[4096 * 2];   // [kxi][h]{er,ei}     inv H-DFT  (e^{+i})
__device__ u64 gB4[2048];       // [j][wp] w-pair      inv W (scaled, signed)

__device__ __forceinline__ u64 f2pack(float a, float b) {
    u64 r; asm("mov.b64 %0,{%1,%2};" : "=l"(r) : "f"(a), "f"(b)); return r;
}
__device__ __forceinline__ u64 splat(float a) {
    u64 r; asm("mov.b64 %0,{%1,%1};" : "=l"(r) : "f"(a)); return r;
}
__device__ __forceinline__ float2 f2unpack(u64 v) {
    float2 r; asm("mov.b64 {%0,%1},%2;" : "=f"(r.x), "=f"(r.y) : "l"(v)); return r;
}
__device__ __forceinline__ u64 fma2(u64 a, u64 b, u64 c) {
    u64 d; asm("fma.rn.f32x2 %0,%1,%2,%3;" : "=l"(d) : "l"(a), "l"(b), "l"(c)); return d;
}

// ---------------- k0: build splatted tables ----------------
__global__ void k0_tables() {
    int id = blockIdx.x * 256 + threadIdx.x;
    float s, c;
    if (id < 2048) {                      // T1: [w][ky]
        int w = id >> 4, ky = id & 15;
        sincospif((float)(ky * w) / 64.f, &s, &c);
        gT1[2 * id] = splat(c); gT1[2 * id + 1] = splat(-s);
    } else if (id < 6144) {               // E2: [h][kxi], e^{-i 2pi ka h/128}
        int e = id - 2048; int h = e >> 5, kx = e & 31;
        int ka = kx < 16 ? kx : kx + 96;
        sincospif((float)(ka * h) / 64.f, &s, &c);
        gE2[2 * e] = splat(c); gE2[2 * e + 1] = splat(-s);
    } else if (id < 10240) {              // E3: [kxi][h], e^{+i 2pi ka h/128}
        int e = id - 6144; int kxi = e >> 7, h = e & 127;
        int ka = kxi < 16 ? kxi : kxi + 96;
        sincospif((float)(ka * h) / 64.f, &s, &c);
        gE3[2 * e] = splat(c); gE3[2 * e + 1] = splat(s);
    } else if (id < 12288) {              // B4: [j=2k+comp][wp]
        int e = id - 10240; int j = e >> 6, wp = e & 63;
        int k = j >> 1, comp = j & 1;
        float sc = (k == 0 ? 1.f : 2.f) / 16384.f;
        float s0, c0, s1, c1;
        sincospif((float)(k * (2 * wp))     / 64.f, &s0, &c0);
        sincospif((float)(k * (2 * wp + 1)) / 64.f, &s1, &c1);
        gB4[e] = comp ? f2pack(-sc * s0, -sc * s1) : f2pack(sc * c0, sc * c1);
    }
}

// ---------------- k1: W-DFT. grid 1024 (bc), block 256. 96KB smem ----------------
// smem: sxp [w][hp] u64 x h-pairs (64KB) | sTW [w][ky]{C,S} ull2 (32KB)
__global__ void __launch_bounds__(256, 2) k1_wdft(const float* __restrict__ x) {
    extern __shared__ char sm1[];
    u64* sxp = (u64*)sm1;                         // 8192 u64
    ulonglong2* sTW = (ulonglong2*)(sm1 + 65536); // 2048 ull2
    const int tid = threadIdx.x, bc = blockIdx.x;

    // copy tables
    for (int i = tid; i < 2048; i += 256) sTW[i] = ((const ulonglong2*)gT1)[i];
    // load + h-pair-pack x
    const float4* xp4 = (const float4*)(x + (size_t)bc * 16384);
    for (int it = 0; it < 8; it++) {
        int unit = it * 256 + tid;                // (a 0..63, w4 0..31)
        int a = unit >> 5, w4 = unit & 31;
        float4 r0 = xp4[(2 * a) * 32 + w4];
        float4 r1 = xp4[(2 * a + 1) * 32 + w4];
        sxp[(4 * w4 + 0) * 64 + a] = f2pack(r0.x, r1.x);
        sxp[(4 * w4 + 1) * 64 + a] = f2pack(r0.y, r1.y);
        sxp[(4 * w4 + 2) * 64 + a] = f2pack(r0.z, r1.z);
        sxp[(4 * w4 + 3) * 64 + a] = f2pack(r0.w, r1.w);
    }
    __syncthreads();

    const int kq = tid & 7;      // ky0 = 2*kq
    const int hg = tid >> 3;     // 0..31, h = 4*hg..4*hg+3
    u64 r00 = 0, r01 = 0, i00 = 0, i01 = 0, r10 = 0, r11 = 0, i10 = 0, i11 = 0;

    #pragma unroll 4
    for (int w = 0; w < 128; w++) {
        ulonglong2 d  = ((const ulonglong2*)sxp)[w * 32 + hg];
        ulonglong2 t0 = sTW[w * 16 + 2 * kq];
        ulonglong2 t1 = sTW[w * 16 + 2 * kq + 1];
        r00 = fma2(d.x, t0.x, r00); i00 = fma2(d.x, t0.y, i00);
        r01 = fma2(d.x, t1.x, r01); i01 = fma2(d.x, t1.y, i01);
        r10 = fma2(d.y, t0.x, r10); i10 = fma2(d.y, t0.y, i10);
        r11 = fma2(d.y, t1.x, r11); i11 = fma2(d.y, t1.y, i11);
    }
    float2 R0 = f2unpack(r00), R1 = f2unpack(r01), I0 = f2unpack(i00), I1 = f2unpack(i01);
    float2 R2 = f2unpack(r10), R3 = f2unpack(r11), I2 = f2unpack(i10), I3 = f2unpack(i11);
    float4* o = g_Xw + ((size_t)bc * 128 + 4 * hg) * 8 + kq;
    o[0]  = make_float4(R0.x, R1.x, I0.x, I1.x);
    o[8]  = make_float4(R0.y, R1.y, I0.y, I1.y);
    o[16] = make_float4(R2.x, R3.x, I2.x, I3.x);
    o[24] = make_float4(R2.y, R3.y, I2.y, I3.y);
}

// ---------------- k2: H-DFT. grid 512 (2 bc), block 128. 96KB smem ----------------
// smem: sE [h][kxi]{er,ei} ull2 (64KB) | sD [sub][h][kyp] float4 (32KB)
__global__ void __launch_bounds__(128, 2) k2_hdft() {
    extern __shared__ char sm2[];
    ulonglong2* sE = (ulonglong2*)sm2;             // 4096 ull2
    float4* sD = (float4*)(sm2 + 65536);           // 2 x 1024
    const int tid = threadIdx.x;
    const int sub = tid >> 6, t = tid & 63;
    const int bc  = blockIdx.x * 2 + sub;

    for (int i = tid; i < 4096; i += 128) sE[i] = ((const ulonglong2*)gE2)[i];
    for (int i = t; i < 1024; i += 64)
        sD[sub * 1024 + i] = g_Xw[(size_t)bc * 1024 + i];
    __syncthreads();

    const int kq  = t >> 3;      // kx0 = 4*kq
    const int kyp = t & 7;       // ky0 = 2*kyp
    const int kx0 = 4 * kq;
    u64 P[4] = {0,0,0,0}, Q[4] = {0,0,0,0}, R[4] = {0,0,0,0}, S[4] = {0,0,0,0};

    #pragma unroll 2
    for (int h = 0; h < 128; h++) {
        ulonglong2 v = ((const ulonglong2*)sD)[sub * 1024 + h * 8 + kyp]; // (xs, ys)
        #pragma unroll
        for (int l = 0; l < 4; l++) {
            ulonglong2 e = sE[h * 32 + kx0 + l];
            P[l] = fma2(v.x, e.x, P[l]);
            Q[l] = fma2(v.y, e.y, Q[l]);
            R[l] = fma2(v.x, e.y, R[l]);
            S[l] = fma2(v.y, e.x, S[l]);
        }
    }
    #pragma unroll
    for (int l = 0; l < 4; l++) {
        float2 p = f2unpack(P[l]), q = f2unpack(Q[l]), r = f2unpack(R[l]), s = f2unpack(S[l]);
        int kx = kx0 + l;
        g_Xf[(size_t)(kx * 16 + 2 * kyp)     * 1024 + bc] = make_float2(p.x - q.x, r.x + s.x);
        g_Xf[(size_t)(kx * 16 + 2 * kyp + 1) * 1024 + bc] = make_float2(p.y - q.y, r.y + s.y);
    }
}

// ---------------- k3: spectral mix per frequency. grid 512, block 256 ----------------
__global__ void __launch_bounds__(256) k3_mix(const float* __restrict__ wr,
                                              const float* __restrict__ wi) {
    __shared__ float2 Xs[1024], Ws[1024];
    const int f = blockIdx.x, kxi = f >> 4, kyy = f & 15;
    const int tid = threadIdx.x;
    for (int idx = tid; idx < 1024; idx += 256) {
        Xs[idx] = g_Xf[(size_t)f * 1024 + idx];
        int i = idx >> 5, o = idx & 31;
        int widx = ((i * 32 + o) * 32 + kxi) * 16 + kyy;
        Ws[idx] = make_float2(wr[widx], wi[widx]);
    }
    __syncthreads();
    const int o = tid & 31, bg = tid >> 5;
    float2 a[4];
    #pragma unroll
    for (int j = 0; j < 4; j++) a[j] = make_float2(0.f, 0.f);
    #pragma unroll 4
    for (int i = 0; i < 32; i++) {
        float2 wv = Ws[i * 32 + o];
        #pragma unroll
        for (int j = 0; j < 4; j++) {
            float2 xv = Xs[(bg + 8 * j) * 32 + i];
            a[j].x = fmaf(xv.x, wv.x, a[j].x); a[j].x = fmaf(-xv.y, wv.y, a[j].x);
            a[j].y = fmaf(xv.x, wv.y, a[j].y); a[j].y = fmaf( xv.y, wv.x, a[j].y);
        }
    }
    #pragma unroll
    for (int j = 0; j < 4; j++)
        g_Yf[(size_t)f * 1024 + (bg + 8 * j) * 32 + o] = a[j];
}

// ---------------- k4: inverse. grid 1024 (bo), block 256. ~100.5KB smem ----------------
// smem: sE3 (64KB) | sB4 (16KB) | sYre (2KB) | sYim (2KB) | y1T [32][132] (16.5KB)
__global__ void __launch_bounds__(256, 2) k4_inv(float* __restrict__ out) {
    extern __shared__ char sm4[];
    ulonglong2* sE3 = (ulonglong2*)sm4;                  // 4096 ull2
    u64*  sB4  = (u64*)(sm4 + 65536);                    // 2048 u64
    float* sYre = (float*)(sm4 + 81920);                 // 512
    float* sYim = (float*)(sm4 + 83968);                 // 512
    float* y1T  = (float*)(sm4 + 86016);                 // 32*132
    const int tid = threadIdx.x, bo = blockIdx.x;

    for (int i = tid; i < 4096; i += 256) sE3[i] = ((const ulonglong2*)gE3)[i];
    for (int i = tid; i < 1024; i += 256) ((ulonglong2*)sB4)[i] = ((const ulonglong2*)gB4)[i];
    for (int i = tid; i < 512; i += 256) {
        float2 v = g_Yf[(size_t)i * 1024 + bo];
        sYre[i] = v.x; sYim[i] = v.y;
    }
    __syncthreads();

    // Stage 1: y1[h][ky] = sum_kxi Yf[kxi][ky] e^{+2pi i kxa h/128}
    {
        const int kyp = tid & 7;       // ky0 = 2*kyp
        const int hs  = tid >> 3;      // h0 = 4*hs
        const int h0  = 4 * hs;
        u64 P[4] = {0,0,0,0}, Q[4] = {0,0,0,0}, R[4] = {0,0,0,0}, S[4] = {0,0,0,0};
        #pragma unroll 2
        for (int kxi = 0; kxi < 32; kxi++) {
            u64 xs = *(const u64*)&sYre[kxi * 16 + 2 * kyp];
            u64 ys = *(const u64*)&sYim[kxi * 16 + 2 * kyp];
            #pragma unroll
            for (int hh = 0; hh < 4; hh++) {
                ulonglong2 e = sE3[kxi * 128 + h0 + hh];
                P[hh] = fma2(xs, e.x, P[hh]);
                Q[hh] = fma2(ys, e.y, Q[hh]);
                R[hh] = fma2(xs, e.y, R[hh]);
                S[hh] = fma2(ys, e.x, S[hh]);
            }
        }
        #pragma unroll
        for (int hh = 0; hh < 4; hh++) {
            float2 p = f2unpack(P[hh]), q = f2unpack(Q[hh]);
            float2 r = f2unpack(R[hh]), s = f2unpack(S[hh]);
            int h = h0 + hh;
            y1T[(4 * kyp)     * 132 + h] = p.x - q.x;   // re ky0
            y1T[(4 * kyp + 1) * 132 + h] = r.x + s.x;   // im ky0
            y1T[(4 * kyp + 2) * 132 + h] = p.y - q.y;   // re ky1
            y1T[(4 * kyp + 3) * 132 + h] = r.y + s.y;   // im ky1
        }
    }
    __syncthreads();

    // Stage 2: real GEMM out[h][w] = sum_j y1T[j][h] * B4[j][w]
    {
        const int ws = tid & 15, hg0 = tid >> 4;
        float* op = out + (size_t)bo * 16384;
        #pragma unroll
        for (int pass = 0; pass < 2; pass++) {
            const int h0 = (hg0 + 16 * pass) * 4;
            u64 acc[4][4];
            #pragma unroll
            for (int hi = 0; hi < 4; hi++)
                #pragma unroll
                for (int m = 0; m < 4; m++) acc[hi][m] = 0ull;
            #pragma unroll 2
            for (int j = 0; j < 32; j++) {
                float4 a = *(const float4*)(y1T + j * 132 + h0);
                u64 a0 = splat(a.x), a1 = splat(a.y), a2 = splat(a.z), a3 = splat(a.w);
                #pragma unroll
                for (int m = 0; m < 4; m++) {
                    u64 b = sB4[j * 64 + ws + 16 * m];
                    acc[0][m] = fma2(a0, b, acc[0][m]);
                    acc[1][m] = fma2(a1, b, acc[1][m]);
                    acc[2][m] = fma2(a2, b, acc[2][m]);
                    acc[3][m] = fma2(a3, b, acc[3][m]);
                }
            }
            #pragma unroll
            for (int hi = 0; hi < 4; hi++)
                #pragma unroll
                for (int m = 0; m < 4; m++)
                    *(float2*)(op + (h0 + hi) * 128 + 2 * (ws + 16 * m)) = f2unpack(acc[hi][m]);
        }
    }
}

// ---------------------------------------------------------------------------
extern "C" void kernel_launch(void* const* d_in, const int* in_sizes, int n_in,
                              void* d_out, int out_size) {
    const float* x  = (const float*)d_in[0];
    const float* wr = (const float*)d_in[1];
    const float* wi = (const float*)d_in[2];
    float* out = (float*)d_out;

    cudaFuncSetAttribute(k1_wdft, cudaFuncAttributeMaxDynamicSharedMemorySize, 98304);
    cudaFuncSetAttribute(k2_hdft, cudaFuncAttributeMaxDynamicSharedMemorySize, 98304);
    cudaFuncSetAttribute(k4_inv,  cudaFuncAttributeMaxDynamicSharedMemorySize, 102912);

    k0_tables<<<48, 256>>>();
    k1_wdft<<<1024, 256, 98304>>>(x);
    k2_hdft<<<512, 128, 98304>>>();
    k3_mix<<<512, 256>>>(wr, wi);
    k4_inv<<<1024, 256, 102912>>>(out);
}

// round 8
// speedup vs baseline: 1.0388x; 1.0388x over previous
#include <cuda_runtime.h>
typedef unsigned long long u64;

// B=32, CIN=COUT=32, H=W=128, M1=M2=16, NMODE=32.
__device__ float4 g_Xw[1024 * 128 * 8];  // [bc][h][kq] (re_ky0,re_ky1,im_ky0,im_ky1) 16MB
__device__ float2 g_Xf[512 * 1024];      // [f][bc]  4MB
__device__ float2 g_Yf[512 * 1024];      // [f][bo]  4MB

// Pre-splatted twiddle tables (built once by k0).
__device__ u64 gT1[2048 * 2];   // [w][ky]{C,S}        fwd W-DFT
__device__ u64 gE2[4096 * 2];   // [h][kxi]{er,ei}     fwd H-DFT  (e^{-i})
__device__ u64 gE3[4096 * 2];   // [kxi][h]{er,ei}     inv H-DFT  (e^{+i})
__device__ u64 gB4[2048];       // [j][wp] w-pair      inv W (scaled, signed)

__device__ __forceinline__ u64 f2pack(float a, float b) {
    u64 r; asm("mov.b64 %0,{%1,%2};" : "=l"(r) : "f"(a), "f"(b)); return r;
}
__device__ __forceinline__ u64 splat(float a) {
    u64 r; asm("mov.b64 %0,{%1,%1};" : "=l"(r) : "f"(a)); return r;
}
__device__ __forceinline__ float2 f2unpack(u64 v) {
    float2 r; asm("mov.b64 {%0,%1},%2;" : "=f"(r.x), "=f"(r.y) : "l"(v)); return r;
}
__device__ __forceinline__ u64 fma2(u64 a, u64 b, u64 c) {
    u64 d; asm("fma.rn.f32x2 %0,%1,%2,%3;" : "=l"(d) : "l"(a), "l"(b), "l"(c)); return d;
}

// ---------------- k0: build splatted tables ----------------
__global__ void k0_tables() {
    int id = blockIdx.x * 256 + threadIdx.x;
    float s, c;
    if (id < 2048) {                      // T1: [w][ky]
        int w = id >> 4, ky = id & 15;
        sincospif((float)(ky * w) / 64.f, &s, &c);
        gT1[2 * id] = splat(c); gT1[2 * id + 1] = splat(-s);
    } else if (id < 6144) {               // E2: [h][kxi], e^{-i 2pi ka h/128}
        int e = id - 2048; int h = e >> 5, kx = e & 31;
        int ka = kx < 16 ? kx : kx + 96;
        sincospif((float)(ka * h) / 64.f, &s, &c);
        gE2[2 * e] = splat(c); gE2[2 * e + 1] = splat(-s);
    } else if (id < 10240) {              // E3: [kxi][h], e^{+i 2pi ka h/128}
        int e = id - 6144; int kxi = e >> 7, h = e & 127;
        int ka = kxi < 16 ? kxi : kxi + 96;
        sincospif((float)(ka * h) / 64.f, &s, &c);
        gE3[2 * e] = splat(c); gE3[2 * e + 1] = splat(s);
    } else if (id < 12288) {              // B4: [j=2k+comp][wp]
        int e = id - 10240; int j = e >> 6, wp = e & 63;
        int k = j >> 1, comp = j & 1;
        float sc = (k == 0 ? 1.f : 2.f) / 16384.f;
        float s0, c0, s1, c1;
        sincospif((float)(k * (2 * wp))     / 64.f, &s0, &c0);
        sincospif((float)(k * (2 * wp + 1)) / 64.f, &s1, &c1);
        gB4[e] = comp ? f2pack(-sc * s0, -sc * s1) : f2pack(sc * c0, sc * c1);
    }
}

// ---------------- k1: W-DFT. grid 1024 (bc), block 256. 96KB smem ----------------
// smem: sxp [w][hp] u64 x h-pairs (64KB) | sTW [w][ky]{C,S} ull2 (32KB)
__global__ void __launch_bounds__(256, 2) k1_wdft(const float* __restrict__ x) {
    extern __shared__ char sm1[];
    u64* sxp = (u64*)sm1;                         // 8192 u64
    ulonglong2* sTW = (ulonglong2*)(sm1 + 65536); // 2048 ull2
    const int tid = threadIdx.x, bc = blockIdx.x;

    // copy tables
    for (int i = tid; i < 2048; i += 256) sTW[i] = ((const ulonglong2*)gT1)[i];
    // load + h-pair-pack x
    const float4* xp4 = (const float4*)(x + (size_t)bc * 16384);
    for (int it = 0; it < 8; it++) {
        int unit = it * 256 + tid;                // (a 0..63, w4 0..31)
        int a = unit >> 5, w4 = unit & 31;
        float4 r0 = xp4[(2 * a) * 32 + w4];
        float4 r1 = xp4[(2 * a + 1) * 32 + w4];
        sxp[(4 * w4 + 0) * 64 + a] = f2pack(r0.x, r1.x);
        sxp[(4 * w4 + 1) * 64 + a] = f2pack(r0.y, r1.y);
        sxp[(4 * w4 + 2) * 64 + a] = f2pack(r0.z, r1.z);
        sxp[(4 * w4 + 3) * 64 + a] = f2pack(r0.w, r1.w);
    }
    __syncthreads();

    const int kq = tid & 7;      // ky0 = 2*kq
    const int hg = tid >> 3;     // 0..31, h = 4*hg..4*hg+3
    u64 r00 = 0, r01 = 0, i00 = 0, i01 = 0, r10 = 0, r11 = 0, i10 = 0, i11 = 0;

    #pragma unroll 4
    for (int w = 0; w < 128; w++) {
        ulonglong2 d  = ((const ulonglong2*)sxp)[w * 32 + hg];
        ulonglong2 t0 = sTW[w * 16 + 2 * kq];
        ulonglong2 t1 = sTW[w * 16 + 2 * kq + 1];
        r00 = fma2(d.x, t0.x, r00); i00 = fma2(d.x, t0.y, i00);
        r01 = fma2(d.x, t1.x, r01); i01 = fma2(d.x, t1.y, i01);
        r10 = fma2(d.y, t0.x, r10); i10 = fma2(d.y, t0.y, i10);
        r11 = fma2(d.y, t1.x, r11); i11 = fma2(d.y, t1.y, i11);
    }
    float2 R0 = f2unpack(r00), R1 = f2unpack(r01), I0 = f2unpack(i00), I1 = f2unpack(i01);
    float2 R2 = f2unpack(r10), R3 = f2unpack(r11), I2 = f2unpack(i10), I3 = f2unpack(i11);
    float4* o = g_Xw + ((size_t)bc * 128 + 4 * hg) * 8 + kq;
    o[0]  = make_float4(R0.x, R1.x, I0.x, I1.x);
    o[8]  = make_float4(R0.y, R1.y, I0.y, I1.y);
    o[16] = make_float4(R2.x, R3.x, I2.x, I3.x);
    o[24] = make_float4(R2.y, R3.y, I2.y, I3.y);
}

// ---------------- k2: H-DFT. grid 512 (2 bc), block 128. 96KB smem ----------------
// smem: sE [h][kxi]{er,ei} ull2 (64KB) | sD [sub][h][kyp] float4 (32KB)
__global__ void __launch_bounds__(128, 2) k2_hdft() {
    extern __shared__ char sm2[];
    ulonglong2* sE = (ulonglong2*)sm2;             // 4096 ull2
    float4* sD = (float4*)(sm2 + 65536);           // 2 x 1024
    const int tid = threadIdx.x;
    const int sub = tid >> 6, t = tid & 63;
    const int bc  = blockIdx.x * 2 + sub;

    for (int i = tid; i < 4096; i += 128) sE[i] = ((const ulonglong2*)gE2)[i];
    for (int i = t; i < 1024; i += 64)
        sD[sub * 1024 + i] = g_Xw[(size_t)bc * 1024 + i];
    __syncthreads();

    const int kq  = t >> 3;      // kx0 = 4*kq
    const int kyp = t & 7;       // ky0 = 2*kyp
    const int kx0 = 4 * kq;
    u64 P[4] = {0,0,0,0}, Q[4] = {0,0,0,0}, R[4] = {0,0,0,0}, S[4] = {0,0,0,0};

    #pragma unroll 2
    for (int h = 0; h < 128; h++) {
        ulonglong2 v = ((const ulonglong2*)sD)[sub * 1024 + h * 8 + kyp]; // (xs, ys)
        #pragma unroll
        for (int l = 0; l < 4; l++) {
            ulonglong2 e = sE[h * 32 + kx0 + l];
            P[l] = fma2(v.x, e.x, P[l]);
            Q[l] = fma2(v.y, e.y, Q[l]);
            R[l] = fma2(v.x, e.y, R[l]);
            S[l] = fma2(v.y, e.x, S[l]);
        }
    }
    #pragma unroll
    for (int l = 0; l < 4; l++) {
        float2 p = f2unpack(P[l]), q = f2unpack(Q[l]), r = f2unpack(R[l]), s = f2unpack(S[l]);
        int kx = kx0 + l;
        g_Xf[(size_t)(kx * 16 + 2 * kyp)     * 1024 + bc] = make_float2(p.x - q.x, r.x + s.x);
        g_Xf[(size_t)(kx * 16 + 2 * kyp + 1) * 1024 + bc] = make_float2(p.y - q.y, r.y + s.y);
    }
}

// ---------------- k3: spectral mix per frequency. grid 512, block 256 ----------------
__global__ void __launch_bounds__(256) k3_mix(const float* __restrict__ wr,
                                              const float* __restrict__ wi) {
    __shared__ float2 Xs[1024], Ws[1024];
    const int f = blockIdx.x, kxi = f >> 4, kyy = f & 15;
    const int tid = threadIdx.x;
    for (int idx = tid; idx < 1024; idx += 256) {
        Xs[idx] = g_Xf[(size_t)f * 1024 + idx];
        int i = idx >> 5, o = idx & 31;
        int widx = ((i * 32 + o) * 32 + kxi) * 16 + kyy;
        Ws[idx] = make_float2(wr[widx], wi[widx]);
    }
    __syncthreads();
    const int o = tid & 31, bg = tid >> 5;
    float2 a[4];
    #pragma unroll
    for (int j = 0; j < 4; j++) a[j] = make_float2(0.f, 0.f);
    #pragma unroll 4
    for (int i = 0; i < 32; i++) {
        float2 wv = Ws[i * 32 + o];
        #pragma unroll
        for (int j = 0; j < 4; j++) {
            float2 xv = Xs[(bg + 8 * j) * 32 + i];
            a[j].x = fmaf(xv.x, wv.x, a[j].x); a[j].x = fmaf(-xv.y, wv.y, a[j].x);
            a[j].y = fmaf(xv.x, wv.y, a[j].y); a[j].y = fmaf( xv.y, wv.x, a[j].y);
        }
    }
    #pragma unroll
    for (int j = 0; j < 4; j++)
        g_Yf[(size_t)f * 1024 + (bg + 8 * j) * 32 + o] = a[j];
}

// ---------------- k4: inverse. grid 1024 (bo), block 256. ~100.5KB smem ----------------
// smem: sE3 (64KB) | sB4 (16KB) | sYre (2KB) | sYim (2KB) | y1T [32][132] (16.5KB)
__global__ void __launch_bounds__(256, 2) k4_inv(float* __restrict__ out) {
    extern __shared__ char sm4[];
    ulonglong2* sE3 = (ulonglong2*)sm4;                  // 4096 ull2
    u64*  sB4  = (u64*)(sm4 + 65536);                    // 2048 u64
    float* sYre = (float*)(sm4 + 81920);                 // 512
    float* sYim = (float*)(sm4 + 83968);                 // 512
    float* y1T  = (float*)(sm4 + 86016);                 // 32*132
    const int tid = threadIdx.x, bo = blockIdx.x;

    for (int i = tid; i < 4096; i += 256) sE3[i] = ((const ulonglong2*)gE3)[i];
    for (int i = tid; i < 1024; i += 256) ((ulonglong2*)sB4)[i] = ((const ulonglong2*)gB4)[i];
    for (int i = tid; i < 512; i += 256) {
        float2 v = g_Yf[(size_t)i * 1024 + bo];
        sYre[i] = v.x; sYim[i] = v.y;
    }
    __syncthreads();

    // Stage 1: y1[h][ky] = sum_kxi Yf[kxi][ky] e^{+2pi i kxa h/128}
    {
        const int kyp = tid & 7;       // ky0 = 2*kyp
        const int hs  = tid >> 3;      // h0 = 4*hs
        const int h0  = 4 * hs;
        u64 P[4] = {0,0,0,0}, Q[4] = {0,0,0,0}, R[4] = {0,0,0,0}, S[4] = {0,0,0,0};
        #pragma unroll 2
        for (int kxi = 0; kxi < 32; kxi++) {
            u64 xs = *(const u64*)&sYre[kxi * 16 + 2 * kyp];
            u64 ys = *(const u64*)&sYim[kxi * 16 + 2 * kyp];
            #pragma unroll
            for (int hh = 0; hh < 4; hh++) {
                ulonglong2 e = sE3[kxi * 128 + h0 + hh];
                P[hh] = fma2(xs, e.x, P[hh]);
                Q[hh] = fma2(ys, e.y, Q[hh]);
                R[hh] = fma2(xs, e.y, R[hh]);
                S[hh] = fma2(ys, e.x, S[hh]);
            }
        }
        #pragma unroll
        for (int hh = 0; hh < 4; hh++) {
            float2 p = f2unpack(P[hh]), q = f2unpack(Q[hh]);
            float2 r = f2unpack(R[hh]), s = f2unpack(S[hh]);
            int h = h0 + hh;
            y1T[(4 * kyp)     * 132 + h] = p.x - q.x;   // re ky0
            y1T[(4 * kyp + 1) * 132 + h] = r.x + s.x;   // im ky0
            y1T[(4 * kyp + 2) * 132 + h] = p.y - q.y;   // re ky1
            y1T[(4 * kyp + 3) * 132 + h] = r.y + s.y;   // im ky1
        }
    }
    __syncthreads();

    // Stage 2: real GEMM out[h][w] = sum_j y1T[j][h] * B4[j][w]
    {
        const int ws = tid & 15, hg0 = tid >> 4;
        float* op = out + (size_t)bo * 16384;
        #pragma unroll
        for (int pass = 0; pass < 2; pass++) {
            const int h0 = (hg0 + 16 * pass) * 4;
            u64 acc[4][4];
            #pragma unroll
            for (int hi = 0; hi < 4; hi++)
                #pragma unroll
                for (int m = 0; m < 4; m++) acc[hi][m] = 0ull;
            #pragma unroll 2
            for (int j = 0; j < 32; j++) {
                float4 a = *(const float4*)(y1T + j * 132 + h0);
                u64 a0 = splat(a.x), a1 = splat(a.y), a2 = splat(a.z), a3 = splat(a.w);
                #pragma unroll
                for (int m = 0; m < 4; m++) {
                    u64 b = sB4[j * 64 + ws + 16 * m];
                    acc[0][m] = fma2(a0, b, acc[0][m]);
                    acc[1][m] = fma2(a1, b, acc[1][m]);
                    acc[2][m] = fma2(a2, b, acc[2][m]);
                    acc[3][m] = fma2(a3, b, acc[3][m]);
                }
            }
            #pragma unroll
            for (int hi = 0; hi < 4; hi++)
                #pragma unroll
                for (int m = 0; m < 4; m++)
                    *(float2*)(op + (h0 + hi) * 128 + 2 * (ws + 16 * m)) = f2unpack(acc[hi][m]);
        }
    }
}

// ---------------------------------------------------------------------------
extern "C" void kernel_launch(void* const* d_in, const int* in_sizes, int n_in,
                              void* d_out, int out_size) {
    const float* x  = (const float*)d_in[0];
    const float* wr = (const float*)d_in[1];
    const float* wi = (const float*)d_in[2];
    float* out = (float*)d_out;

    cudaFuncSetAttribute(k1_wdft, cudaFuncAttributeMaxDynamicSharedMemorySize, 98304);
    cudaFuncSetAttribute(k2_hdft, cudaFuncAttributeMaxDynamicSharedMemorySize, 98304);
    cudaFuncSetAttribute(k4_inv,  cudaFuncAttributeMaxDynamicSharedMemorySize, 102912);

    k0_tables<<<48, 256>>>();
    k1_wdft<<<1024, 256, 98304>>>(x);
    k2_hdft<<<512, 128, 98304>>>();
    k3_mix<<<512, 256>>>(wr, wi);
    k4_inv<<<1024, 256, 102912>>>(out);
}

// round 10
// speedup vs baseline: 1.0424x; 1.0035x over previous
#include <cuda_runtime.h>
typedef unsigned long long u64;

// B=32, CIN=COUT=32, H=W=128, M1=M2=16, NMODE=32.
__device__ float4 g_Xw[1024 * 128 * 8];  // [bc][h][kq] (re_ky0,re_ky1,im_ky0,im_ky1) 16MB
__device__ float2 g_Xf[512 * 1024];      // [f][bc]  4MB
__device__ float2 g_Yf[512 * 1024];      // [f][bo]  4MB

// Pre-splatted twiddle tables (built once by k0).
__device__ u64 gT1[2048 * 2];   // [w][ky]{C,S}        fwd W-DFT
__device__ u64 gE2[4096 * 2];   // [h][kxi]{er,ei}     fwd H-DFT  (e^{-i})
__device__ u64 gE3[4096 * 2];   // [kxi][h]{er,ei}     inv H-DFT  (e^{+i})
__device__ u64 gB4[2048];       // [j][wp] w-pair      inv W (scaled, signed)

__device__ __forceinline__ u64 f2pack(float a, float b) {
    u64 r; asm("mov.b64 %0,{%1,%2};" : "=l"(r) : "f"(a), "f"(b)); return r;
}
__device__ __forceinline__ u64 splat(float a) {
    u64 r; asm("mov.b64 %0,{%1,%1};" : "=l"(r) : "f"(a)); return r;
}
__device__ __forceinline__ float2 f2unpack(u64 v) {
    float2 r; asm("mov.b64 {%0,%1},%2;" : "=f"(r.x), "=f"(r.y) : "l"(v)); return r;
}
__device__ __forceinline__ u64 fma2(u64 a, u64 b, u64 c) {
    u64 d; asm("fma.rn.f32x2 %0,%1,%2,%3;" : "=l"(d) : "l"(a), "l"(b), "l"(c)); return d;
}

// ---------------- k0: build splatted tables ----------------
__global__ void k0_tables() {
    int id = blockIdx.x * 256 + threadIdx.x;
    float s, c;
    if (id < 2048) {                      // T1: [w][ky]
        int w = id >> 4, ky = id & 15;
        sincospif((float)(ky * w) / 64.f, &s, &c);
        gT1[2 * id] = splat(c); gT1[2 * id + 1] = splat(-s);
    } else if (id < 6144) {               // E2: [h][kxi], e^{-i 2pi ka h/128}
        int e = id - 2048; int h = e >> 5, kx = e & 31;
        int ka = kx < 16 ? kx : kx + 96;
        sincospif((float)(ka * h) / 64.f, &s, &c);
        gE2[2 * e] = splat(c); gE2[2 * e + 1] = splat(-s);
    } else if (id < 10240) {              // E3: [kxi][h], e^{+i 2pi ka h/128}
        int e = id - 6144; int kxi = e >> 7, h = e & 127;
        int ka = kxi < 16 ? kxi : kxi + 96;
        sincospif((float)(ka * h) / 64.f, &s, &c);
        gE3[2 * e] = splat(c); gE3[2 * e + 1] = splat(s);
    } else if (id < 12288) {              // B4: [j=2k+comp][wp]
        int e = id - 10240; int j = e >> 6, wp = e & 63;
        int k = j >> 1, comp = j & 1;
        float sc = (k == 0 ? 1.f : 2.f) / 16384.f;
        float s0, c0, s1, c1;
        sincospif((float)(k * (2 * wp))     / 64.f, &s0, &c0);
        sincospif((float)(k * (2 * wp + 1)) / 64.f, &s1, &c1);
        gB4[e] = comp ? f2pack(-sc * s0, -sc * s1) : f2pack(sc * c0, sc * c1);
    }
}

// ---------------- k1: W-DFT. grid 1024 (bc), block 256. 96KB smem ----------------
// smem: sxp [w][hp] u64 x h-pairs (64KB) | sTW [w][ky]{C,S} ull2 (32KB)
__global__ void __launch_bounds__(256, 2) k1_wdft(const float* __restrict__ x) {
    extern __shared__ char sm1[];
    u64* sxp = (u64*)sm1;                         // 8192 u64
    ulonglong2* sTW = (ulonglong2*)(sm1 + 65536); // 2048 ull2
    const int tid = threadIdx.x, bc = blockIdx.x;

    // copy tables
    for (int i = tid; i < 2048; i += 256) sTW[i] = ((const ulonglong2*)gT1)[i];
    // load + h-pair-pack x
    const float4* xp4 = (const float4*)(x + (size_t)bc * 16384);
    for (int it = 0; it < 8; it++) {
        int unit = it * 256 + tid;                // (a 0..63, w4 0..31)
        int a = unit >> 5, w4 = unit & 31;
        float4 r0 = xp4[(2 * a) * 32 + w4];
        float4 r1 = xp4[(2 * a + 1) * 32 + w4];
        sxp[(4 * w4 + 0) * 64 + a] = f2pack(r0.x, r1.x);
        sxp[(4 * w4 + 1) * 64 + a] = f2pack(r0.y, r1.y);
        sxp[(4 * w4 + 2) * 64 + a] = f2pack(r0.z, r1.z);
        sxp[(4 * w4 + 3) * 64 + a] = f2pack(r0.w, r1.w);
    }
    __syncthreads();

    const int kq = tid & 7;      // ky0 = 2*kq
    const int hg = tid >> 3;     // 0..31, h = 4*hg..4*hg+3
    u64 r00 = 0, r01 = 0, i00 = 0, i01 = 0, r10 = 0, r11 = 0, i10 = 0, i11 = 0;

    #pragma unroll 4
    for (int w = 0; w < 128; w++) {
        ulonglong2 d  = ((const ulonglong2*)sxp)[w * 32 + hg];
        ulonglong2 t0 = sTW[w * 16 + 2 * kq];
        ulonglong2 t1 = sTW[w * 16 + 2 * kq + 1];
        r00 = fma2(d.x, t0.x, r00); i00 = fma2(d.x, t0.y, i00);
        r01 = fma2(d.x, t1.x, r01); i01 = fma2(d.x, t1.y, i01);
        r10 = fma2(d.y, t0.x, r10); i10 = fma2(d.y, t0.y, i10);
        r11 = fma2(d.y, t1.x, r11); i11 = fma2(d.y, t1.y, i11);
    }
    float2 R0 = f2unpack(r00), R1 = f2unpack(r01), I0 = f2unpack(i00), I1 = f2unpack(i01);
    float2 R2 = f2unpack(r10), R3 = f2unpack(r11), I2 = f2unpack(i10), I3 = f2unpack(i11);
    float4* o = g_Xw + ((size_t)bc * 128 + 4 * hg) * 8 + kq;
    o[0]  = make_float4(R0.x, R1.x, I0.x, I1.x);
    o[8]  = make_float4(R0.y, R1.y, I0.y, I1.y);
    o[16] = make_float4(R2.x, R3.x, I2.x, I3.x);
    o[24] = make_float4(R2.y, R3.y, I2.y, I3.y);
}

// ---------------- k2: H-DFT. grid 512 (2 bc), block 128. 96KB smem ----------------
// smem: sE [h][kxi]{er,ei} ull2 (64KB) | sD [sub][h][kyp] float4 (32KB)
__global__ void __launch_bounds__(128, 2) k2_hdft() {
    extern __shared__ char sm2[];
    ulonglong2* sE = (ulonglong2*)sm2;             // 4096 ull2
    float4* sD = (float4*)(sm2 + 65536);           // 2 x 1024
    const int tid = threadIdx.x;
    const int sub = tid >> 6, t = tid & 63;
    const int bc  = blockIdx.x * 2 + sub;

    for (int i = tid; i < 4096; i += 128) sE[i] = ((const ulonglong2*)gE2)[i];
    for (int i = t; i < 1024; i += 64)
        sD[sub * 1024 + i] = g_Xw[(size_t)bc * 1024 + i];
    __syncthreads();

    const int kq  = t >> 3;      // kx0 = 4*kq
    const int kyp = t & 7;       // ky0 = 2*kyp
    const int kx0 = 4 * kq;
    u64 P[4] = {0,0,0,0}, Q[4] = {0,0,0,0}, R[4] = {0,0,0,0}, S[4] = {0,0,0,0};

    #pragma unroll 2
    for (int h = 0; h < 128; h++) {
        ulonglong2 v = ((const ulonglong2*)sD)[sub * 1024 + h * 8 + kyp]; // (xs, ys)
        #pragma unroll
        for (int l = 0; l < 4; l++) {
            ulonglong2 e = sE[h * 32 + kx0 + l];
            P[l] = fma2(v.x, e.x, P[l]);
            Q[l] = fma2(v.y, e.y, Q[l]);
            R[l] = fma2(v.x, e.y, R[l]);
            S[l] = fma2(v.y, e.x, S[l]);
        }
    }
    #pragma unroll
    for (int l = 0; l < 4; l++) {
        float2 p = f2unpack(P[l]), q = f2unpack(Q[l]), r = f2unpack(R[l]), s = f2unpack(S[l]);
        int kx = kx0 + l;
        g_Xf[(size_t)(kx * 16 + 2 * kyp)     * 1024 + bc] = make_float2(p.x - q.x, r.x + s.x);
        g_Xf[(size_t)(kx * 16 + 2 * kyp + 1) * 1024 + bc] = make_float2(p.y - q.y, r.y + s.y);
    }
}

// ---------------- k3: spectral mix per frequency. grid 512, block 256 ----------------
__global__ void __launch_bounds__(256) k3_mix(const float* __restrict__ wr,
                                              const float* __restrict__ wi) {
    __shared__ float2 Xs[1024], Ws[1024];
    const int f = blockIdx.x, kxi = f >> 4, kyy = f & 15;
    const int tid = threadIdx.x;
    for (int idx = tid; idx < 1024; idx += 256) {
        Xs[idx] = g_Xf[(size_t)f * 1024 + idx];
        int i = idx >> 5, o = idx & 31;
        int widx = ((i * 32 + o) * 32 + kxi) * 16 + kyy;
        Ws[idx] = make_float2(wr[widx], wi[widx]);
    }
    __syncthreads();
    const int o = tid & 31, bg = tid >> 5;
    float2 a[4];
    #pragma unroll
    for (int j = 0; j < 4; j++) a[j] = make_float2(0.f, 0.f);
    #pragma unroll 4
    for (int i = 0; i < 32; i++) {
        float2 wv = Ws[i * 32 + o];
        #pragma unroll
        for (int j = 0; j < 4; j++) {
            float2 xv = Xs[(bg + 8 * j) * 32 + i];
            a[j].x = fmaf(xv.x, wv.x, a[j].x); a[j].x = fmaf(-xv.y, wv.y, a[j].x);
            a[j].y = fmaf(xv.x, wv.y, a[j].y); a[j].y = fmaf( xv.y, wv.x, a[j].y);
        }
    }
    #pragma unroll
    for (int j = 0; j < 4; j++)
        g_Yf[(size_t)f * 1024 + (bg + 8 * j) * 32 + o] = a[j];
}

// ---------------- k4: inverse. grid 1024 (bo), block 256. ~100.5KB smem ----------------
// smem: sE3 (64KB) | sB4 (16KB) | sYre (2KB) | sYim (2KB) | y1T [32][132] (16.5KB)
__global__ void __launch_bounds__(256, 2) k4_inv(float* __restrict__ out) {
    extern __shared__ char sm4[];
    ulonglong2* sE3 = (ulonglong2*)sm4;                  // 4096 ull2
    u64*  sB4  = (u64*)(sm4 + 65536);                    // 2048 u64
    float* sYre = (float*)(sm4 + 81920);                 // 512
    float* sYim = (float*)(sm4 + 83968);                 // 512
    float* y1T  = (float*)(sm4 + 86016);                 // 32*132
    const int tid = threadIdx.x, bo = blockIdx.x;

    for (int i = tid; i < 4096; i += 256) sE3[i] = ((const ulonglong2*)gE3)[i];
    for (int i = tid; i < 1024; i += 256) ((ulonglong2*)sB4)[i] = ((const ulonglong2*)gB4)[i];
    for (int i = tid; i < 512; i += 256) {
        float2 v = g_Yf[(size_t)i * 1024 + bo];
        sYre[i] = v.x; sYim[i] = v.y;
    }
    __syncthreads();

    // Stage 1: y1[h][ky] = sum_kxi Yf[kxi][ky] e^{+2pi i kxa h/128}
    {
        const int kyp = tid & 7;       // ky0 = 2*kyp
        const int hs  = tid >> 3;      // h0 = 4*hs
        const int h0  = 4 * hs;
        u64 P[4] = {0,0,0,0}, Q[4] = {0,0,0,0}, R[4] = {0,0,0,0}, S[4] = {0,0,0,0};
        #pragma unroll 2
        for (int kxi = 0; kxi < 32; kxi++) {
            u64 xs = *(const u64*)&sYre[kxi * 16 + 2 * kyp];
            u64 ys = *(const u64*)&sYim[kxi * 16 + 2 * kyp];
            #pragma unroll
            for (int hh = 0; hh < 4; hh++) {
                ulonglong2 e = sE3[kxi * 128 + h0 + hh];
                P[hh] = fma2(xs, e.x, P[hh]);
                Q[hh] = fma2(ys, e.y, Q[hh]);
                R[hh] = fma2(xs, e.y, R[hh]);
                S[hh] = fma2(ys, e.x, S[hh]);
            }
        }
        #pragma unroll
        for (int hh = 0; hh < 4; hh++) {
            float2 p = f2unpack(P[hh]), q = f2unpack(Q[hh]);
            float2 r = f2unpack(R[hh]), s = f2unpack(S[hh]);
            int h = h0 + hh;
            y1T[(4 * kyp)     * 132 + h] = p.x - q.x;   // re ky0
            y1T[(4 * kyp + 1) * 132 + h] = r.x + s.x;   // im ky0
            y1T[(4 * kyp + 2) * 132 + h] = p.y - q.y;   // re ky1
            y1T[(4 * kyp + 3) * 132 + h] = r.y + s.y;   // im ky1
        }
    }
    __syncthreads();

    // Stage 2: real GEMM out[h][w] = sum_j y1T[j][h] * B4[j][w]
    {
        const int ws = tid & 15, hg0 = tid >> 4;
        float* op = out + (size_t)bo * 16384;
        #pragma unroll
        for (int pass = 0; pass < 2; pass++) {
            const int h0 = (hg0 + 16 * pass) * 4;
            u64 acc[4][4];
            #pragma unroll
            for (int hi = 0; hi < 4; hi++)
                #pragma unroll
                for (int m = 0; m < 4; m++) acc[hi][m] = 0ull;
            #pragma unroll 2
            for (int j = 0; j < 32; j++) {
                float4 a = *(const float4*)(y1T + j * 132 + h0);
                u64 a0 = splat(a.x), a1 = splat(a.y), a2 = splat(a.z), a3 = splat(a.w);
                #pragma unroll
                for (int m = 0; m < 4; m++) {
                    u64 b = sB4[j * 64 + ws + 16 * m];
                    acc[0][m] = fma2(a0, b, acc[0][m]);
                    acc[1][m] = fma2(a1, b, acc[1][m]);
                    acc[2][m] = fma2(a2, b, acc[2][m]);
                    acc[3][m] = fma2(a3, b, acc[3][m]);
                }
            }
            #pragma unroll
            for (int hi = 0; hi < 4; hi++)
                #pragma unroll
                for (int m = 0; m < 4; m++)
                    *(float2*)(op + (h0 + hi) * 128 + 2 * (ws + 16 * m)) = f2unpack(acc[hi][m]);
        }
    }
}

// ---------------------------------------------------------------------------
extern "C" void kernel_launch(void* const* d_in, const int* in_sizes, int n_in,
                              void* d_out, int out_size) {
    const float* x  = (const float*)d_in[0];
    const float* wr = (const float*)d_in[1];
    const float* wi = (const float*)d_in[2];
    float* out = (float*)d_out;

    cudaFuncSetAttribute(k1_wdft, cudaFuncAttributeMaxDynamicSharedMemorySize, 98304);
    cudaFuncSetAttribute(k2_hdft, cudaFuncAttributeMaxDynamicSharedMemorySize, 98304);
    cudaFuncSetAttribute(k4_inv,  cudaFuncAttributeMaxDynamicSharedMemorySize, 102912);

    k0_tables<<<48, 256>>>();
    k1_wdft<<<1024, 256, 98304>>>(x);
    k2_hdft<<<512, 128, 98304>>>();
    k3_mix<<<512, 256>>>(wr, wi);
    k4_inv<<<1024, 256, 102912>>>(out);
}

// round 12
// speedup vs baseline: 1.5240x; 1.4619x over previous
#include <cuda_runtime.h>
typedef unsigned long long u64;

// B=32, CIN=COUT=32, H=W=128, M1=M2=16, NMODE=32.
__device__ float2 g_Xw[1024 * 16 * 128];  // [bc][ky][h]   16 MB
__device__ float2 g_Xf[512 * 1024];       // [f][bc]        4 MB
__device__ float2 g_Yf[512 * 1024];       // [f][bo]        4 MB

// Tables for k4 (built once per launch by k0).
__device__ ulonglong2 gE3[4096];  // [kxi][h] {splat cos, splat sin}, e^{+2pi i ka h/128}
__device__ u64 gB4[2048];         // [j=2k+comp][wp] packed w-pair, scaled/signed

__device__ __forceinline__ u64 f2pack(float a, float b) {
    u64 r; asm("mov.b64 %0,{%1,%2};" : "=l"(r) : "f"(a), "f"(b)); return r;
}
__device__ __forceinline__ u64 splat(float a) {
    u64 r; asm("mov.b64 %0,{%1,%1};" : "=l"(r) : "f"(a)); return r;
}
__device__ __forceinline__ float2 f2unpack(u64 v) {
    float2 r; asm("mov.b64 {%0,%1},%2;" : "=f"(r.x), "=f"(r.y) : "l"(v)); return r;
}
__device__ __forceinline__ u64 fma2(u64 a, u64 b, u64 c) {
    u64 d; asm("fma.rn.f32x2 %0,%1,%2,%3;" : "=l"(d) : "l"(a), "l"(b), "l"(c)); return d;
}
__device__ __forceinline__ float2 cmul(float2 a, float2 b) {
    return make_float2(fmaf(a.x, b.x, -a.y * b.y), fmaf(a.x, b.y, a.y * b.x));
}

// ---------------- k0: k4 tables ----------------
__global__ void k0_tables() {
    int id = blockIdx.x * 256 + threadIdx.x;
    float s, c;
    if (id < 4096) {                        // E3: [kxi][h]
        int kxi = id >> 7, h = id & 127;
        int ka = kxi < 16 ? kxi : kxi + 96;
        sincospif((float)(ka * h) / 64.f, &s, &c);
        ulonglong2 v; v.x = splat(c); v.y = splat(s);
        gE3[id] = v;
    } else if (id < 6144) {                 // B4: [j][wp]
        int e = id - 4096; int j = e >> 6, wp = e & 63;
        int k = j >> 1, comp = j & 1;
        float sc = (k == 0 ? 1.f : 2.f) / 16384.f;
        float s0, c0, s1, c1;
        sincospif((float)(k * (2 * wp))     / 64.f, &s0, &c0);
        sincospif((float)(k * (2 * wp + 1)) / 64.f, &s1, &c1);
        gB4[e] = comp ? f2pack(-sc * s0, -sc * s1) : f2pack(sc * c0, sc * c1);
    }
}

// ---------------- k1: W-DFT (Round-2 version, measured-good) ----------------
__global__ void __launch_bounds__(256, 4) k1_wdft(const float* __restrict__ x) {
    const int bc   = blockIdx.x >> 1;
    const int half = blockIdx.x & 1;
    const int tid  = threadIdx.x;
    const int ky   = tid & 15;
    const int hb   = tid >> 4;
    const int h0 = half * 64 + hb;
    const float4* p0 = (const float4*)x + (size_t)bc * 4096 + h0 * 32;
    const float4* p1 = p0 + 512;
    const float4* p2 = p0 + 1024;
    const float4* p3 = p0 + 1536;

    float2 tw0, tw1, tw2, tw3, s4;
    {
        float s, c;
        tw0 = make_float2(1.f, 0.f);
        sincospif(-(float)ky       / 64.f, &s, &c); tw1 = make_float2(c, s);
        sincospif(-(float)(2 * ky) / 64.f, &s, &c); tw2 = make_float2(c, s);
        sincospif(-(float)(3 * ky) / 64.f, &s, &c); tw3 = make_float2(c, s);
        sincospif(-(float)(4 * ky) / 64.f, &s, &c); s4  = make_float2(c, s);
    }
    float2 a0 = {0.f,0.f}, a1 = {0.f,0.f}, a2 = {0.f,0.f}, a3 = {0.f,0.f};
#define K1_ACC(TW, C)                                             \
    a0.x = fmaf(v0.C, TW.x, a0.x); a0.y = fmaf(v0.C, TW.y, a0.y); \
    a1.x = fmaf(v1.C, TW.x, a1.x); a1.y = fmaf(v1.C, TW.y, a1.y); \
    a2.x = fmaf(v2.C, TW.x, a2.x); a2.y = fmaf(v2.C, TW.y, a2.y); \
    a3.x = fmaf(v3.C, TW.x, a3.x); a3.y = fmaf(v3.C, TW.y, a3.y);
    #pragma unroll 2
    for (int w4 = 0; w4 < 32; w4++) {
        float4 v0 = p0[w4], v1 = p1[w4], v2 = p2[w4], v3 = p3[w4];
        K1_ACC(tw0, x) K1_ACC(tw1, y) K1_ACC(tw2, z) K1_ACC(tw3, w)
        tw0 = cmul(tw0, s4); tw1 = cmul(tw1, s4);
        tw2 = cmul(tw2, s4); tw3 = cmul(tw3, s4);
    }
#undef K1_ACC
    float2* o = g_Xw + ((size_t)bc * 16 + ky) * 128 + h0;
    o[0] = a0; o[16] = a1; o[32] = a2; o[48] = a3;
}

// ---------------- k2: H-DFT (Round-2 version) ----------------
__global__ void __launch_bounds__(256, 8) k2_hdft() {
    __shared__ float2 xw[16][130];
    const int bc  = blockIdx.x;
    const int tid = threadIdx.x;
    const float2* src = g_Xw + (size_t)bc * 2048;
    for (int idx = tid; idx < 2048; idx += 256)
        xw[idx >> 7][idx & 127] = src[idx];
    __syncthreads();

    const int ky2 = tid & 7;
    const int kxi = tid >> 3;
    const int kx  = (kxi < 16) ? kxi : (kxi + 96);
    float s, c;
    sincospif(-(float)kx / 64.f, &s, &c);
    const float2 st = make_float2(c, s);
    float2 t  = make_float2(1.f, 0.f);
    float2 aA = {0.f,0.f}, aB = {0.f,0.f};
    #pragma unroll 4
    for (int h = 0; h < 128; h++) {
        float2 vA = xw[ky2][h];
        float2 vB = xw[ky2 + 8][h];
        aA.x = fmaf(vA.x, t.x, aA.x); aA.x = fmaf(-vA.y, t.y, aA.x);
        aA.y = fmaf(vA.x, t.y, aA.y); aA.y = fmaf( vA.y, t.x, aA.y);
        aB.x = fmaf(vB.x, t.x, aB.x); aB.x = fmaf(-vB.y, t.y, aB.x);
        aB.y = fmaf(vB.x, t.y, aB.y); aB.y = fmaf( vB.y, t.x, aB.y);
        t = cmul(t, st);
    }
    g_Xf[((size_t)kxi * 16 + ky2)     * 1024 + bc] = aA;
    g_Xf[((size_t)kxi * 16 + ky2 + 8) * 1024 + bc] = aB;
}

// ---------------- k3: spectral mix (Round-2 version) ----------------
__global__ void __launch_bounds__(256, 8) k3_mix(const float* __restrict__ wr,
                                                 const float* __restrict__ wi) {
    __shared__ float2 Xs[1024], Ws[1024];
    const int f = blockIdx.x, kxi = f >> 4, kyy = f & 15;
    const int tid = threadIdx.x;
    for (int idx = tid; idx < 1024; idx += 256) {
        Xs[idx] = g_Xf[(size_t)f * 1024 + idx];
        int i = idx >> 5, o = idx & 31;
        int widx = ((i * 32 + o) * 32 + kxi) * 16 + kyy;
        Ws[idx] = make_float2(wr[widx], wi[widx]);
    }
    __syncthreads();
    const int o = tid & 31, bg = tid >> 5;
    float2 a[4];
    #pragma unroll
    for (int j = 0; j < 4; j++) a[j] = make_float2(0.f, 0.f);
    #pragma unroll 4
    for (int i = 0; i < 32; i++) {
        float2 wv = Ws[i * 32 + o];
        #pragma unroll
        for (int j = 0; j < 4; j++) {
            float2 xv = Xs[(bg + 8 * j) * 32 + i];
            a[j].x = fmaf(xv.x, wv.x, a[j].x); a[j].x = fmaf(-xv.y, wv.y, a[j].x);
            a[j].y = fmaf(xv.x, wv.y, a[j].y); a[j].y = fmaf( xv.y, wv.x, a[j].y);
        }
    }
    #pragma unroll
    for (int j = 0; j < 4; j++)
        g_Yf[(size_t)f * 1024 + (bg + 8 * j) * 32 + o] = a[j];
}

// ---------------- k4: inverse, FFMA2 + smem tables (Round-4 version) ----------------
// smem: sE3 64KB | sB4 16KB | sYre 2KB | sYim 2KB | y1T [32][132] 16.5KB  = 100.5KB
__global__ void __launch_bounds__(256, 2) k4_inv(float* __restrict__ out) {
    extern __shared__ char sm4[];
    ulonglong2* sE3 = (ulonglong2*)sm4;
    u64*  sB4  = (u64*)(sm4 + 65536);
    float* sYre = (float*)(sm4 + 81920);
    float* sYim = (float*)(sm4 + 83968);
    float* y1T  = (float*)(sm4 + 86016);
    const int tid = threadIdx.x, bo = blockIdx.x;

    for (int i = tid; i < 4096; i += 256) sE3[i] = gE3[i];
    for (int i = tid; i < 1024; i += 256) ((ulonglong2*)sB4)[i] = ((const ulonglong2*)gB4)[i];
    for (int i = tid; i < 512; i += 256) {
        float2 v = g_Yf[(size_t)i * 1024 + bo];
        sYre[i] = v.x; sYim[i] = v.y;
    }
    __syncthreads();

    // Stage 1: y1[h][ky] = sum_kxi Yf[kxi][ky] e^{+2pi i kxa h/128}, ky-pair lanes.
    {
        const int kyp = tid & 7;
        const int h0  = 4 * (tid >> 3);
        u64 P[4] = {0,0,0,0}, Q[4] = {0,0,0,0}, R[4] = {0,0,0,0}, S[4] = {0,0,0,0};
        #pragma unroll 2
        for (int kxi = 0; kxi < 32; kxi++) {
            u64 xs = *(const u64*)&sYre[kxi * 16 + 2 * kyp];
            u64 ys = *(const u64*)&sYim[kxi * 16 + 2 * kyp];
            #pragma unroll
            for (int hh = 0; hh < 4; hh++) {
                ulonglong2 e = sE3[kxi * 128 + h0 + hh];
                P[hh] = fma2(xs, e.x, P[hh]);
                Q[hh] = fma2(ys, e.y, Q[hh]);
                R[hh] = fma2(xs, e.y, R[hh]);
                S[hh] = fma2(ys, e.x, S[hh]);
            }
        }
        #pragma unroll
        for (int hh = 0; hh < 4; hh++) {
            float2 p = f2unpack(P[hh]), q = f2unpack(Q[hh]);
            float2 r = f2unpack(R[hh]), s = f2unpack(S[hh]);
            int h = h0 + hh;
            y1T[(4 * kyp)     * 132 + h] = p.x - q.x;
            y1T[(4 * kyp + 1) * 132 + h] = r.x + s.x;
            y1T[(4 * kyp + 2) * 132 + h] = p.y - q.y;
            y1T[(4 * kyp + 3) * 132 + h] = r.y + s.y;
        }
    }
    __syncthreads();

    // Stage 2: real GEMM out[h][w] = sum_j y1T[j][h] * B4[j][w], w-pair lanes.
    {
        const int ws = tid & 15, hg0 = tid >> 4;
        float* op = out + (size_t)bo * 16384;
        #pragma unroll
        for (int pass = 0; pass < 2; pass++) {
            const int h0 = (hg0 + 16 * pass) * 4;
            u64 acc[4][4];
            #pragma unroll
            for (int hi = 0; hi < 4; hi++)
                #pragma unroll
                for (int m = 0; m < 4; m++) acc[hi][m] = 0ull;
            #pragma unroll 2
            for (int j = 0; j < 32; j++) {
                float4 a = *(const float4*)(y1T + j * 132 + h0);
                u64 a0 = splat(a.x), a1 = splat(a.y), a2 = splat(a.z), a3 = splat(a.w);
                #pragma unroll
                for (int m = 0; m < 4; m++) {
                    u64 b = sB4[j * 64 + ws + 16 * m];
                    acc[0][m] = fma2(a0, b, acc[0][m]);
                    acc[1][m] = fma2(a1, b, acc[1][m]);
                    acc[2][m] = fma2(a2, b, acc[2][m]);
                    acc[3][m] = fma2(a3, b, acc[3][m]);
                }
            }
            #pragma unroll
            for (int hi = 0; hi < 4; hi++)
                #pragma unroll
                for (int m = 0; m < 4; m++)
                    *(float2*)(op + (h0 + hi) * 128 + 2 * (ws + 16 * m)) = f2unpack(acc[hi][m]);
        }
    }
}

// ---------------------------------------------------------------------------
extern "C" void kernel_launch(void* const* d_in, const int* in_sizes, int n_in,
                              void* d_out, int out_size) {
    const float* x  = (const float*)d_in[0];
    const float* wr = (const float*)d_in[1];
    const float* wi = (const float*)d_in[2];
    float* out = (float*)d_out;

    cudaFuncSetAttribute(k4_inv, cudaFuncAttributeMaxDynamicSharedMemorySize, 102912);

    k0_tables<<<24, 256>>>();
    k1_wdft<<<2048, 256>>>(x);
    k2_hdft<<<1024, 256>>>();
    k3_mix<<<512, 256>>>(wr, wi);
    k4_inv<<<1024, 256, 102912>>>(out);
}